// round 2
// baseline (speedup 1.0000x reference)
#include <cuda_runtime.h>
#include <cstdint>
#include <cstddef>

// Problem dims (fixed by reference)
#define BB    64
#define TT    512
#define IDIM  512
#define HH    512
#define KTOT  1024          // concatenated K: [input | hidden]
#define RING  4             // h1 ring buffer depth

// Tiling
#define TM    16            // rows per CTA tile
#define TN    32            // cols per CTA tile
#define NBAND (BB/TM)       // 4 row bands
#define NQ    (HH/TN)       // 16 col groups
#define CTAS_PER_LAYER (NBAND*NQ)   // 64
#define NCTA  (2*CTAS_PER_LAYER)    // 128
#define NTHR  128
#define AS_STRIDE 1028      // padded row stride (floats) for A tile in smem

// Device-global scratch (no allocation allowed)
__device__ float g_h1[RING][BB][HH];       // layer-1 hidden ring
__device__ int   g_done1[TT*NBAND];        // layer-1 per-(step,band) completion
__device__ int   g_done2[TT*NBAND];        // layer-2 per-(step,band) completion

__global__ void rnn_init_counters() {
    int i = blockIdx.x * blockDim.x + threadIdx.x;
    if (i < TT*NBAND) { g_done1[i] = 0; g_done2[i] = 0; }
}

__device__ __forceinline__ int ld_acq(const int* p) {
    int v;
    asm volatile("ld.acquire.gpu.global.u32 %0, [%1];" : "=r"(v) : "l"(p));
    return v;
}

__device__ __forceinline__ float4 ldcg4(const float* p) {
    return __ldcg((const float4*)p);
}

__global__ void __launch_bounds__(NTHR, 1) rnn_persistent(
    const float* __restrict__ x,    // [B,T,I]
    const float* __restrict__ h0,   // [L,B,H]
    const float* __restrict__ Wih,  // [L,H,I]
    const float* __restrict__ bih,  // [L,H]
    const float* __restrict__ Whh,  // [L,H,H]
    const float* __restrict__ bhh,  // [L,H]
    float* __restrict__ out)        // [B,T,H] then [L,B,H]
{
    extern __shared__ float smem[];
    float* Ws = smem;                    // [KTOT][TN] transposed weights
    float* As = smem + KTOT*TN;          // [TM][AS_STRIDE] A tile

    const int bx    = blockIdx.x;
    const int layer = bx >> 6;           // 0 or 1
    const int j     = bx & 63;
    const int r     = j >> 4;            // row band 0..3
    const int q     = j & 15;            // col group 0..15
    const int tid   = threadIdx.x;

    const float* Wi = Wih + (size_t)layer * HH * IDIM;
    const float* Wh = Whh + (size_t)layer * HH * HH;

    // ---- Load this CTA's 32x1024 weight slice into SMEM, transposed Ws[k][n] ----
    for (int idx = tid; idx < TN*512; idx += NTHR) {
        int n = idx >> 9;          // 0..31
        int k = idx & 511;         // coalesced along k
        Ws[k*TN + n]        = Wi[(size_t)(q*TN + n)*IDIM + k];
        Ws[(512+k)*TN + n]  = Wh[(size_t)(q*TN + n)*HH   + k];
    }

    // Thread micro-tile: 1 row x 4 cols
    const int m    = tid & 15;           // row in tile
    const int ng   = tid >> 4;           // col group-of-4 (0..7)
    const int n0   = ng * 4;
    const int brow = r*TM + m;           // global batch row
    const int hcol = q*TN + n0;          // global hidden col

    float4 bias;
    bias.x = bih[layer*HH + hcol+0] + bhh[layer*HH + hcol+0];
    bias.y = bih[layer*HH + hcol+1] + bhh[layer*HH + hcol+1];
    bias.z = bih[layer*HH + hcol+2] + bhh[layer*HH + hcol+2];
    bias.w = bih[layer*HH + hcol+3] + bhh[layer*HH + hcol+3];

    __syncthreads();

    for (int t = 0; t < TT; ++t) {
        // ---- dependency waits (thread 0 spins, then CTA barrier) ----
        if (tid == 0) {
            if (layer == 0) {
                if (t > 0)
                    while (ld_acq(&g_done1[(t-1)*NBAND + r]) < NQ) __nanosleep(32);
                if (t >= RING)   // ring-slot overwrite guard (L2 readers of h1[t-RING])
                    while (ld_acq(&g_done2[(t-RING)*NBAND + r]) < NQ) __nanosleep(32);
            } else {
                while (ld_acq(&g_done1[t*NBAND + r]) < NQ) __nanosleep(32);
                if (t > 0)
                    while (ld_acq(&g_done2[(t-1)*NBAND + r]) < NQ) __nanosleep(32);
            }
        }
        __syncthreads();

        // ---- load A tile: 16 rows x 1024 cols (as 4096 float4) ----
        #pragma unroll 4
        for (int c = 0; c < 32; ++c) {
            int lin = tid + c*NTHR;      // 0..4095
            int mm  = lin >> 8;          // row 0..15
            int kk  = lin & 255;         // float4 index, k = 4*kk
            int b   = r*TM + mm;
            float4 v;
            if (layer == 0) {
                if (kk < 128) {
                    v = __ldg((const float4*)(x + ((size_t)b*TT + t)*IDIM) + kk);
                } else {
                    const float* hp = (t == 0) ? (h0 + (size_t)b*HH)
                                               : &g_h1[(t-1)&(RING-1)][b][0];
                    v = ldcg4(hp + (kk-128)*4);
                }
            } else {
                if (kk < 128) {
                    v = ldcg4(&g_h1[t&(RING-1)][b][0] + kk*4);
                } else {
                    const float* hp = (t == 0) ? (h0 + (size_t)BB*HH + (size_t)b*HH)
                                               : (out + ((size_t)b*TT + (t-1))*HH);
                    v = ldcg4(hp + (kk-128)*4);
                }
            }
            *(float4*)&As[mm*AS_STRIDE + kk*4] = v;
        }
        __syncthreads();

        // ---- main GEMM micro-kernel: 4 outputs, K=1024, packed f32x2 FMAs ----
        unsigned long long acc0 = 0ull, acc1 = 0ull;   // {c0,c1}, {c2,c3}
        const float* Arow = &As[m*AS_STRIDE];
        #pragma unroll 16
        for (int k = 0; k < KTOT; ++k) {
            float a = Arow[k];
            unsigned long long aa;
            asm("mov.b64 %0, {%1, %2};" : "=l"(aa) : "f"(a), "f"(a));
            ulonglong2 bb = *(const ulonglong2*)&Ws[k*TN + n0];
            asm("fma.rn.f32x2 %0, %1, %2, %0;" : "+l"(acc0) : "l"(aa), "l"(bb.x));
            asm("fma.rn.f32x2 %0, %1, %2, %0;" : "+l"(acc1) : "l"(aa), "l"(bb.y));
        }
        float c0, c1, c2, c3;
        asm("mov.b64 {%0, %1}, %2;" : "=f"(c0), "=f"(c1) : "l"(acc0));
        asm("mov.b64 {%0, %1}, %2;" : "=f"(c2), "=f"(c3) : "l"(acc1));

        float4 res;
        res.x = tanhf(c0 + bias.x);
        res.y = tanhf(c1 + bias.y);
        res.z = tanhf(c2 + bias.z);
        res.w = tanhf(c3 + bias.w);

        // ---- store results ----
        if (layer == 0) {
            *(float4*)&g_h1[t&(RING-1)][brow][hcol] = res;
            if (t == TT-1)   // hidden_final[0]
                *(float4*)(out + (size_t)BB*TT*HH + (size_t)brow*HH + hcol) = res;
        } else {
            *(float4*)(out + ((size_t)brow*TT + t)*HH + hcol) = res;
            if (t == TT-1)   // hidden_final[1]
                *(float4*)(out + (size_t)BB*TT*HH + (size_t)BB*HH
                               + (size_t)brow*HH + hcol) = res;
        }

        // ---- publish: fence stores, then signal completion ----
        __threadfence();
        __syncthreads();
        if (tid == 0) {
            int* ctr = (layer == 0) ? &g_done1[t*NBAND + r] : &g_done2[t*NBAND + r];
            atomicAdd(ctr, 1);
        }
    }
}

extern "C" void kernel_launch(void* const* d_in, const int* in_sizes, int n_in,
                              void* d_out, int out_size)
{
    const float* x   = (const float*)d_in[0];
    const float* h0  = (const float*)d_in[1];
    const float* Wih = (const float*)d_in[2];
    const float* bih = (const float*)d_in[3];
    const float* Whh = (const float*)d_in[4];
    const float* bhh = (const float*)d_in[5];
    float* out = (float*)d_out;

    const size_t smem_bytes = (size_t)(KTOT*TN + TM*AS_STRIDE) * sizeof(float); // ~192 KB
    cudaFuncSetAttribute(rnn_persistent,
                         cudaFuncAttributeMaxDynamicSharedMemorySize,
                         (int)smem_bytes);

    rnn_init_counters<<<(TT*NBAND + 255)/256, 256>>>();
    rnn_persistent<<<NCTA, NTHR, smem_bytes>>>(x, h0, Wih, bih, Whh, bhh, out);
}

// round 3
// speedup vs baseline: 1.3805x; 1.3805x over previous
#include <cuda_runtime.h>
#include <cstdint>
#include <cstddef>

// Problem dims (fixed by reference)
#define BB    64
#define TT    512
#define IDIM  512
#define HH    512
#define KTOT  1024          // concatenated K: [input | hidden]
#define RING  4             // h1 ring buffer depth

// Tiling
#define TM    16            // rows per CTA tile
#define TN    32            // cols per CTA tile
#define NBAND (BB/TM)       // 4 row bands
#define NQ    (HH/TN)       // 16 col groups
#define CTAS_PER_LAYER (NBAND*NQ)   // 64
#define NCTA  (2*CTAS_PER_LAYER)    // 128
#define NTHR  256
#define AS_STRIDE 1028      // padded row stride (floats), 16B-aligned, bank-skewed

// Device-global scratch (no allocation allowed)
__device__ float g_h1[RING][BB][HH];       // layer-1 hidden ring
__device__ int   g_done1[TT*NBAND];        // layer-1 per-(step,band) completion
__device__ int   g_done2[TT*NBAND];        // layer-2 per-(step,band) completion

__global__ void rnn_init_counters() {
    int i = blockIdx.x * blockDim.x + threadIdx.x;
    if (i < TT*NBAND) { g_done1[i] = 0; g_done2[i] = 0; }
}

__device__ __forceinline__ int ld_acq(const int* p) {
    int v;
    asm volatile("ld.acquire.gpu.global.u32 %0, [%1];" : "=r"(v) : "l"(p));
    return v;
}

__device__ __forceinline__ void red_release(int* p) {
    asm volatile("red.release.gpu.global.add.u32 [%0], %1;" :: "l"(p), "r"(1) : "memory");
}

__device__ __forceinline__ void fma2(unsigned long long& acc,
                                     unsigned long long a,
                                     unsigned long long b) {
    asm("fma.rn.f32x2 %0, %1, %2, %0;" : "+l"(acc) : "l"(a), "l"(b));
}

__device__ __forceinline__ float4 ldcg4(const float* p) {
    return __ldcg((const float4*)p);
}

__global__ void __launch_bounds__(NTHR, 1) rnn_persistent(
    const float* __restrict__ x,    // [B,T,I]
    const float* __restrict__ h0,   // [L,B,H]
    const float* __restrict__ Wih,  // [L,H,I]
    const float* __restrict__ bih,  // [L,H]
    const float* __restrict__ Whh,  // [L,H,H]
    const float* __restrict__ bhh,  // [L,H]
    float* __restrict__ out)        // [B,T,H] then [L,B,H]
{
    extern __shared__ float smem[];
    float* Ws = smem;                    // paired weights: [512 kp][32 n][2] floats (128 KB)
    float* As = smem + 512*TN*2;         // A tile [TM][AS_STRIDE]

    const int bx    = blockIdx.x;
    const int layer = bx >> 6;           // 0 or 1
    const int j     = bx & 63;
    const int r     = j >> 4;            // row band 0..3
    const int q     = j & 15;            // col group 0..15
    const int tid   = threadIdx.x;

    const float* Wi = Wih + (size_t)layer * HH * IDIM;
    const float* Wh = Whh + (size_t)layer * HH * HH;

    // ---- Load 32x1024 weight slice into SMEM as K-pairs: Ws[kp][n] = {w(n,2kp), w(n,2kp+1)} ----
    // x-part: kp 0..255 ; h-part: kp 256..511
    for (int idx = tid; idx < TN*256; idx += NTHR) {
        int n  = idx >> 8;         // 0..31
        int kp = idx & 255;        // coalesced along kp
        float2 vi = __ldg((const float2*)(Wi + (size_t)(q*TN + n)*IDIM) + kp);
        float2 vh = __ldg((const float2*)(Wh + (size_t)(q*TN + n)*HH)   + kp);
        *(float2*)&Ws[(kp*TN + n)*2]        = vi;
        *(float2*)&Ws[((256+kp)*TN + n)*2]  = vh;
    }

    // Thread micro-tile: 1 row x 2 cols. Warp covers 8 rows x 8 cols
    // (keeps per-warp SMEM footprint low: A 128B/4k, W 128B/4k).
    const int w    = tid >> 5;
    const int lane = tid & 31;
    const int rb   = w >> 2;                  // 0..1  (row block of 8)
    const int cb   = w & 3;                   // 0..3  (col block of 8)
    const int m    = rb*8 + (lane >> 2);      // 0..15 row in tile
    const int n0   = (cb*4 + (lane & 3))*2;   // 0,2,...,30  col pair base
    const int brow = r*TM + m;                // global batch row
    const int hcol = q*TN + n0;               // global hidden col

    float2 bias;
    bias.x = bih[layer*HH + hcol+0] + bhh[layer*HH + hcol+0];
    bias.y = bih[layer*HH + hcol+1] + bhh[layer*HH + hcol+1];

    __syncthreads();

    for (int t = 0; t < TT; ++t) {
        // ============ stage A tile (16 x 1024) with overlapped waits ============
        // Each half is 2048 float4; 256 threads -> 8 iters; lin>>7 = row, lin&127 = f4 col.
        if (layer == 0) {
            // x-half has no dependency: prefetch before any wait
            #pragma unroll
            for (int c = 0; c < 8; ++c) {
                int lin = tid + c*NTHR;
                int mm  = lin >> 7, kk = lin & 127;
                float4 v = __ldg((const float4*)(x + ((size_t)(r*TM+mm)*TT + t)*IDIM) + kk);
                *(float4*)&As[mm*AS_STRIDE + kk*4] = v;
            }
            if (tid == 0) {
                if (t > 0)
                    while (ld_acq(&g_done1[(t-1)*NBAND + r]) < NQ) { }
                if (t >= RING)   // ring-slot overwrite guard
                    while (ld_acq(&g_done2[(t-RING)*NBAND + r]) < NQ) { }
            }
            __syncthreads();
            #pragma unroll
            for (int c = 0; c < 8; ++c) {
                int lin = tid + c*NTHR;
                int mm  = lin >> 7, kk = lin & 127;
                int b   = r*TM + mm;
                const float* hp = (t == 0) ? (h0 + (size_t)b*HH)
                                           : &g_h1[(t-1)&(RING-1)][b][0];
                float4 v = ldcg4(hp + kk*4);
                *(float4*)&As[mm*AS_STRIDE + (128+kk)*4] = v;
            }
        } else {
            // h2(t-1) half: waits on own layer's previous step (cheap)
            if (tid == 0 && t > 0)
                while (ld_acq(&g_done2[(t-1)*NBAND + r]) < NQ) { }
            __syncthreads();
            #pragma unroll
            for (int c = 0; c < 8; ++c) {
                int lin = tid + c*NTHR;
                int mm  = lin >> 7, kk = lin & 127;
                int b   = r*TM + mm;
                const float* hp = (t == 0) ? (h0 + (size_t)BB*HH + (size_t)b*HH)
                                           : (out + ((size_t)b*TT + (t-1))*HH);
                float4 v = ldcg4(hp + kk*4);
                *(float4*)&As[mm*AS_STRIDE + (128+kk)*4] = v;
            }
            if (tid == 0)
                while (ld_acq(&g_done1[t*NBAND + r]) < NQ) { }
            __syncthreads();
            #pragma unroll
            for (int c = 0; c < 8; ++c) {
                int lin = tid + c*NTHR;
                int mm  = lin >> 7, kk = lin & 127;
                int b   = r*TM + mm;
                float4 v = ldcg4(&g_h1[t&(RING-1)][b][0] + kk*4);
                *(float4*)&As[mm*AS_STRIDE + kk*4] = v;
            }
        }
        __syncthreads();

        // ============ GEMM micro-kernel: 2 outputs, K=1024, paired-K FMA2 ============
        // acc = {sum over even k, sum over odd k}; horizontal add at the end.
        unsigned long long acc0 = 0ull, acc1 = 0ull;
        const float* Arow = &As[m*AS_STRIDE];
        const float* Wp   = &Ws[n0*2];
        #pragma unroll 8
        for (int jj = 0; jj < 256; ++jj) {          // 4 k per iteration
            ulonglong2 a2 = *(const ulonglong2*)(Arow + jj*4);          // {a0,a1},{a2,a3}
            ulonglong2 w0 = *(const ulonglong2*)(Wp + (2*jj)*TN*2);     // cols n0,n0+1 @ kp=2jj
            ulonglong2 w1 = *(const ulonglong2*)(Wp + (2*jj+1)*TN*2);   // @ kp=2jj+1
            fma2(acc0, a2.x, w0.x);
            fma2(acc1, a2.x, w0.y);
            fma2(acc0, a2.y, w1.x);
            fma2(acc1, a2.y, w1.y);
        }
        float e0, o0, e1, o1;
        asm("mov.b64 {%0, %1}, %2;" : "=f"(e0), "=f"(o0) : "l"(acc0));
        asm("mov.b64 {%0, %1}, %2;" : "=f"(e1), "=f"(o1) : "l"(acc1));

        float2 res;
        res.x = tanhf(e0 + o0 + bias.x);
        res.y = tanhf(e1 + o1 + bias.y);

        // ---- store results ----
        if (layer == 0) {
            *(float2*)&g_h1[t&(RING-1)][brow][hcol] = res;
            if (t == TT-1)   // hidden_final[0]
                *(float2*)(out + (size_t)BB*TT*HH + (size_t)brow*HH + hcol) = res;
        } else {
            *(float2*)(out + ((size_t)brow*TT + t)*HH + hcol) = res;
            if (t == TT-1)   // hidden_final[1]
                *(float2*)(out + (size_t)BB*TT*HH + (size_t)BB*HH
                               + (size_t)brow*HH + hcol) = res;
        }

        // ---- publish: CTA barrier orders all stores, release-atomic signals ----
        __syncthreads();
        if (tid == 0) {
            int* ctr = (layer == 0) ? &g_done1[t*NBAND + r] : &g_done2[t*NBAND + r];
            red_release(ctr);
        }
    }
}

extern "C" void kernel_launch(void* const* d_in, const int* in_sizes, int n_in,
                              void* d_out, int out_size)
{
    const float* x   = (const float*)d_in[0];
    const float* h0  = (const float*)d_in[1];
    const float* Wih = (const float*)d_in[2];
    const float* bih = (const float*)d_in[3];
    const float* Whh = (const float*)d_in[4];
    const float* bhh = (const float*)d_in[5];
    float* out = (float*)d_out;

    const size_t smem_bytes = (size_t)(512*TN*2 + TM*AS_STRIDE) * sizeof(float); // ~192 KB
    cudaFuncSetAttribute(rnn_persistent,
                         cudaFuncAttributeMaxDynamicSharedMemorySize,
                         (int)smem_bytes);

    rnn_init_counters<<<(TT*NBAND + 255)/256, 256>>>();
    rnn_persistent<<<NCTA, NTHR, smem_bytes>>>(x, h0, Wih, bih, Whh, bhh, out);
}

// round 4
// speedup vs baseline: 2.0648x; 1.4956x over previous
#include <cuda_runtime.h>
#include <cstdint>
#include <cstddef>

// Problem dims
#define BB    64
#define TT    512
#define IDIM  512
#define HH    512
#define KTOT  1024
#define RING  4

// Tiling
#define TM    16
#define TN    32
#define NBAND (BB/TM)       // 4
#define NQ    (HH/TN)       // 16
#define NCTA  128
#define NTHR  256
#define RSTRIDE 528         // Red row stride (512 + 16 pad)

// SMEM layout (floats): As[512*32] | Ws[512*64] | Red[8*528]
#define AS_OFF  0
#define WS_OFF  (512*32)
#define RED_OFF (512*32 + 512*64)
#define SMEM_FLOATS (512*32 + 512*64 + 8*RSTRIDE)

__device__ float g_h1[RING][BB][HH];
__device__ int   g_done1[TT*NBAND];
__device__ int   g_done2[TT*NBAND];

__global__ void rnn_init_counters() {
    int i = blockIdx.x * blockDim.x + threadIdx.x;
    if (i < TT*NBAND) { g_done1[i] = 0; g_done2[i] = 0; }
}

__device__ __forceinline__ int ld_acq(const int* p) {
    int v;
    asm volatile("ld.acquire.gpu.global.u32 %0, [%1];" : "=r"(v) : "l"(p));
    return v;
}
__device__ __forceinline__ void red_release(int* p) {
    asm volatile("red.release.gpu.global.add.u32 [%0], %1;" :: "l"(p), "r"(1) : "memory");
}
__device__ __forceinline__ void fma2(unsigned long long& acc,
                                     unsigned long long a, unsigned long long b) {
    asm("fma.rn.f32x2 %0, %1, %2, %0;" : "+l"(acc) : "l"(a), "l"(b));
}
__device__ __forceinline__ float4 ldcg4(const float* p) {
    return __ldcg((const float4*)p);
}

// Store one source float4 (4 consecutive k for row mm) into k-paired As
__device__ __forceinline__ void stage_pair(float* As, int K0, int mm, float4 v) {
    // k = 4*K0.. : kp = 2*K0 holds {k,k+1}, kp = 2*K0+1 holds {k+2,k+3}
    float2* p0 = (float2*)&As[(2*K0)    *32 + mm*2];
    float2* p1 = (float2*)&As[(2*K0 + 1)*32 + mm*2];
    *p0 = make_float2(v.x, v.y);
    *p1 = make_float2(v.z, v.w);
}

__global__ void __launch_bounds__(NTHR, 1) rnn_persistent(
    const float* __restrict__ x,
    const float* __restrict__ h0,
    const float* __restrict__ Wih,
    const float* __restrict__ bih,
    const float* __restrict__ Whh,
    const float* __restrict__ bhh,
    float* __restrict__ out)
{
    extern __shared__ float smem[];
    float* As  = smem + AS_OFF;   // [512 kp][32]  : As[kp*32 + m*2 + e] = A[2kp+e][m]
    float* Ws  = smem + WS_OFF;   // [512 kp][64]  : Ws[kp*64 + c*2 + e] = W[c][2kp+e]
    float* Red = smem + RED_OFF;  // [8 w][528]    : partials per output

    const int bx    = blockIdx.x;
    const int layer = bx >> 6;
    const int j     = bx & 63;
    const int r     = j >> 4;            // row band
    const int q     = j & 15;            // col group
    const int tid   = threadIdx.x;
    const int w     = tid >> 5;          // warp id = k-slice (kp range [64w,64w+64))
    const int lane  = tid & 31;
    const int rg    = lane & 3;          // rows 4rg..4rg+3
    const int cg    = lane >> 2;         // cols {2cg,2cg+1,16+2cg,17+2cg}

    const float* Wi = Wih + (size_t)layer * HH * IDIM;
    const float* Wh = Whh + (size_t)layer * HH * HH;

    // ---- one-time: load 32x1024 weight slice, k-paired transposed ----
    for (int idx = tid; idx < TN*256; idx += NTHR) {
        int c   = idx >> 8;        // 0..31
        int kpl = idx & 255;       // 0..255
        float2 vi = __ldg((const float2*)(Wi + (size_t)(q*TN + c)*IDIM) + kpl);
        float2 vh = __ldg((const float2*)(Wh + (size_t)(q*TN + c)*HH)   + kpl);
        *(float2*)&Ws[(size_t)kpl*64 + c*2]       = vi;
        *(float2*)&Ws[(size_t)(256+kpl)*64 + c*2] = vh;
    }

    // ---- output-side mapping (for reduce/store): 2 outputs per thread ----
    const int o0     = 2*tid;                // output index m*32+c
    const int m_out  = o0 >> 5;
    const int c_out  = o0 & 31;
    const int brow_o = r*TM + m_out;
    const int hcol_o = q*TN + c_out;
    float2 bias;
    bias.x = bih[layer*HH + hcol_o]   + bhh[layer*HH + hcol_o];
    bias.y = bih[layer*HH + hcol_o+1] + bhh[layer*HH + hcol_o+1];

    __syncthreads();

    const float* Ap0 = As + (size_t)(64*w)*32 + rg*8;
    const float* Wp0 = Ws + (size_t)(64*w)*64 + cg*4;

    for (int t = 0; t < TT; ++t) {
        // ============ stage A tile (k-paired), overlapping waits ============
        // Each half: 2048 float4; mapping: mm = lin&15 (varies across lanes), K0h = lin>>4
        if (layer == 0) {
            // x-half (K0 0..127): no dependency — prefetch
            #pragma unroll
            for (int c = 0; c < 8; ++c) {
                int lin = tid + c*NTHR;
                int mm = lin & 15, K0h = lin >> 4;
                float4 v = __ldg((const float4*)(x + ((size_t)(r*TM+mm)*TT + t)*IDIM) + K0h);
                stage_pair(As, K0h, mm, v);
            }
            if (tid == 0) {
                if (t > 0)
                    while (ld_acq(&g_done1[(t-1)*NBAND + r]) < NQ) { }
                if (t >= RING)
                    while (ld_acq(&g_done2[(t-RING)*NBAND + r]) < NQ) { }
            }
            __syncthreads();
            #pragma unroll
            for (int c = 0; c < 8; ++c) {
                int lin = tid + c*NTHR;
                int mm = lin & 15, K0h = lin >> 4;
                int b  = r*TM + mm;
                const float* hp = (t == 0) ? (h0 + (size_t)b*HH)
                                           : &g_h1[(t-1)&(RING-1)][b][0];
                stage_pair(As, 128 + K0h, mm, ldcg4(hp + K0h*4));
            }
        } else {
            if (tid == 0 && t > 0)
                while (ld_acq(&g_done2[(t-1)*NBAND + r]) < NQ) { }
            __syncthreads();
            #pragma unroll
            for (int c = 0; c < 8; ++c) {
                int lin = tid + c*NTHR;
                int mm = lin & 15, K0h = lin >> 4;
                int b  = r*TM + mm;
                const float* hp = (t == 0) ? (h0 + (size_t)BB*HH + (size_t)b*HH)
                                           : (out + ((size_t)b*TT + (t-1))*HH);
                stage_pair(As, 128 + K0h, mm, ldcg4(hp + K0h*4));
            }
            if (tid == 0)
                while (ld_acq(&g_done1[t*NBAND + r]) < NQ) { }
            __syncthreads();
            #pragma unroll
            for (int c = 0; c < 8; ++c) {
                int lin = tid + c*NTHR;
                int mm = lin & 15, K0h = lin >> 4;
                int b  = r*TM + mm;
                stage_pair(As, K0h, mm, ldcg4(&g_h1[t&(RING-1)][b][0] + K0h*4));
            }
        }
        __syncthreads();

        // ============ GEMM: warp k-slice, thread 4x4, k-paired FMA2 ============
        unsigned long long acc[16];
        #pragma unroll
        for (int i = 0; i < 16; ++i) acc[i] = 0ull;

        const float* Ap = Ap0;
        const float* Wp = Wp0;
        #pragma unroll 4
        for (int kp = 0; kp < 64; ++kp) {
            ulonglong2 A0 = *(const ulonglong2*)(Ap);       // rows m0,  m0+1
            ulonglong2 A1 = *(const ulonglong2*)(Ap + 4);   // rows m0+2,m0+3
            ulonglong2 W0 = *(const ulonglong2*)(Wp);       // cols 2cg, 2cg+1
            ulonglong2 W1 = *(const ulonglong2*)(Wp + 32);  // cols 16+2cg, 17+2cg
            fma2(acc[ 0], A0.x, W0.x); fma2(acc[ 1], A0.x, W0.y);
            fma2(acc[ 2], A0.x, W1.x); fma2(acc[ 3], A0.x, W1.y);
            fma2(acc[ 4], A0.y, W0.x); fma2(acc[ 5], A0.y, W0.y);
            fma2(acc[ 6], A0.y, W1.x); fma2(acc[ 7], A0.y, W1.y);
            fma2(acc[ 8], A1.x, W0.x); fma2(acc[ 9], A1.x, W0.y);
            fma2(acc[10], A1.x, W1.x); fma2(acc[11], A1.x, W1.y);
            fma2(acc[12], A1.y, W0.x); fma2(acc[13], A1.y, W0.y);
            fma2(acc[14], A1.y, W1.x); fma2(acc[15], A1.y, W1.y);
            Ap += 32; Wp += 64;
        }

        // horizontal add (even+odd) and write partials to Red[w]
        {
            float s[16];
            #pragma unroll
            for (int i = 0; i < 16; ++i) {
                float lo, hi;
                asm("mov.b64 {%0, %1}, %2;" : "=f"(lo), "=f"(hi) : "l"(acc[i]));
                s[i] = lo + hi;
            }
            float* Rw = Red + w*RSTRIDE + (rg*4)*32 + cg*2;
            #pragma unroll
            for (int i = 0; i < 4; ++i) {
                *(float2*)(Rw + i*32)      = make_float2(s[i*4+0], s[i*4+1]);
                *(float2*)(Rw + i*32 + 16) = make_float2(s[i*4+2], s[i*4+3]);
            }
        }
        __syncthreads();

        // ============ cross-warp reduce, bias, tanh, store ============
        float2 acc2 = make_float2(0.f, 0.f);
        #pragma unroll
        for (int ww = 0; ww < 8; ++ww) {
            float2 v = *(const float2*)(Red + ww*RSTRIDE + o0);
            acc2.x += v.x; acc2.y += v.y;
        }
        float2 res;
        res.x = tanhf(acc2.x + bias.x);
        res.y = tanhf(acc2.y + bias.y);

        if (layer == 0) {
            *(float2*)&g_h1[t&(RING-1)][brow_o][hcol_o] = res;
            if (t == TT-1)
                *(float2*)(out + (size_t)BB*TT*HH + (size_t)brow_o*HH + hcol_o) = res;
        } else {
            *(float2*)(out + ((size_t)brow_o*TT + t)*HH + hcol_o) = res;
            if (t == TT-1)
                *(float2*)(out + (size_t)BB*TT*HH + (size_t)BB*HH
                               + (size_t)brow_o*HH + hcol_o) = res;
        }

        __syncthreads();
        if (tid == 0) {
            int* ctr = (layer == 0) ? &g_done1[t*NBAND + r] : &g_done2[t*NBAND + r];
            red_release(ctr);
        }
    }
}

extern "C" void kernel_launch(void* const* d_in, const int* in_sizes, int n_in,
                              void* d_out, int out_size)
{
    const float* x   = (const float*)d_in[0];
    const float* h0  = (const float*)d_in[1];
    const float* Wih = (const float*)d_in[2];
    const float* bih = (const float*)d_in[3];
    const float* Whh = (const float*)d_in[4];
    const float* bhh = (const float*)d_in[5];
    float* out = (float*)d_out;

    const size_t smem_bytes = (size_t)SMEM_FLOATS * sizeof(float); // ~208.5 KB
    cudaFuncSetAttribute(rnn_persistent,
                         cudaFuncAttributeMaxDynamicSharedMemorySize,
                         (int)smem_bytes);

    rnn_init_counters<<<(TT*NBAND + 255)/256, 256>>>();
    rnn_persistent<<<NCTA, NTHR, smem_bytes>>>(x, h0, Wih, bih, Whh, bhh, out);
}

// round 5
// speedup vs baseline: 2.9696x; 1.4382x over previous
#include <cuda_runtime.h>
#include <cstdint>
#include <cstddef>

// Problem dims
#define BB    64
#define TT    512
#define IDIM  512
#define HH    512
#define RING  8

// Tiling
#define TM    16
#define TN    32
#define NBAND (BB/TM)       // 4
#define NQ    (HH/TN)       // 16
#define NCTA  128
#define NTHR  256

#define AS_STRIDE 1028      // floats per As row (16B aligned; gives 2-group row-bank spread)
#define RMS 34              // Red m-stride (floats) -> conflict-free partial STS
#define RWS (16*RMS)        // 544 floats per warp

// SMEM layout (floats)
#define AS_OFF  0
#define WS_OFF  (TM*AS_STRIDE)              // 16448
#define RED_OFF (WS_OFF + 512*64)           // + 32768
#define SMEM_FLOATS (RED_OFF + 8*RWS)       // + 4352  = 53568 floats (~209.3 KB)

__device__ float g_h1[RING][BB][HH];
__device__ int   g_done1[TT*NBAND];
__device__ int   g_done2[TT*NBAND];

__global__ void rnn_init_counters() {
    int i = blockIdx.x * blockDim.x + threadIdx.x;
    if (i < TT*NBAND) { g_done1[i] = 0; g_done2[i] = 0; }
}

__device__ __forceinline__ int ld_acq(const int* p) {
    int v;
    asm volatile("ld.acquire.gpu.global.u32 %0, [%1];" : "=r"(v) : "l"(p));
    return v;
}
__device__ __forceinline__ void red_release(int* p) {
    asm volatile("red.release.gpu.global.add.u32 [%0], %1;" :: "l"(p), "r"(1) : "memory");
}
__device__ __forceinline__ void fma2(unsigned long long& acc,
                                     unsigned long long a, unsigned long long b) {
    asm("fma.rn.f32x2 %0, %1, %2, %0;" : "+l"(acc) : "l"(a), "l"(b));
}
__device__ __forceinline__ float4 ldcg4(const float* p) {
    return __ldcg((const float4*)p);
}

// Store one float4 (k = 4*kk .. 4*kk+3 of row mm) into swizzled row-major As.
// Swizzle: float-index within row = (4*kk) ^ (8*(mm>>2))  (permutes 32B blocks).
__device__ __forceinline__ void stage_f4(float* As, int mm, int kk, float4 v) {
    int idx = (kk*4) ^ ((mm >> 2) * 8);
    *(float4*)&As[mm*AS_STRIDE + idx] = v;
}

__global__ void __launch_bounds__(NTHR, 1) rnn_persistent(
    const float* __restrict__ x,    // [B,T,I]
    const float* __restrict__ h0,   // [L,B,H]
    const float* __restrict__ Wih,  // [L,H,I]
    const float* __restrict__ bih,  // [L,H]
    const float* __restrict__ Whh,  // [L,H,H]
    const float* __restrict__ bhh,  // [L,H]
    float* __restrict__ out)        // [B,T,H] then [L,B,H]
{
    extern __shared__ float smem[];
    float* As  = smem + AS_OFF;   // [16][1028] row-major, k-index XOR-swizzled
    float* Ws  = smem + WS_OFF;   // [512 kp][64] : Ws[kp*64 + c*2 + e] = W[c][2kp+e]
    float* Red = smem + RED_OFF;  // [8 w][16 m x RMS]

    const int bx    = blockIdx.x;
    const int layer = bx >> 6;
    const int j     = bx & 63;
    const int r     = j >> 4;            // row band
    const int q     = j & 15;            // col group
    const int tid   = threadIdx.x;
    const int w     = tid >> 5;          // warp id = k-slice: kp in [64w, 64w+64)
    const int lane  = tid & 31;
    const int rg    = lane & 3;          // rows 4rg..4rg+3
    const int cg    = lane >> 2;         // cols {2cg,2cg+1,16+2cg,17+2cg}

    const float* Wi = Wih + (size_t)layer * HH * IDIM;
    const float* Wh = Whh + (size_t)layer * HH * HH;

    // ---- one-time weight load: k-paired transposed; k-low = Wih, k-high = Whh ----
    for (int idx = tid; idx < TN*256; idx += NTHR) {
        int c   = idx >> 8;        // 0..31
        int kpl = idx & 255;       // 0..255
        float2 vi = __ldg((const float2*)(Wi + (size_t)(q*TN + c)*IDIM) + kpl);
        float2 vh = __ldg((const float2*)(Wh + (size_t)(q*TN + c)*HH)   + kpl);
        *(float2*)&Ws[(size_t)kpl*64 + c*2]       = vi;
        *(float2*)&Ws[(size_t)(256+kpl)*64 + c*2] = vh;
    }

    // ---- output-side mapping (reduce/store): 2 outputs per thread ----
    const int o0     = 2*tid;
    const int m_out  = o0 >> 5;
    const int c_out  = o0 & 31;
    const int brow_o = r*TM + m_out;
    const int hcol_o = q*TN + c_out;
    float2 bias;
    bias.x = bih[layer*HH + hcol_o]   + bhh[layer*HH + hcol_o];
    bias.y = bih[layer*HH + hcol_o+1] + bhh[layer*HH + hcol_o+1];

    __syncthreads();

    const float* Ab  = As + (4*rg)*AS_STRIDE;
    const int    xr  = 8*rg;                          // XOR swizzle constant for this thread's rows
    const float* Wp0 = Ws + (size_t)(64*w)*64 + cg*4;

    for (int t = 0; t < TT; ++t) {
        // ================= waits + staging =================
        if (layer == 0) {
            // x half (k 0..511): no dependency — stage immediately (coalesced)
            #pragma unroll
            for (int c = 0; c < 8; ++c) {
                int lin = tid + c*NTHR;
                int mm = lin >> 7, kk = lin & 127;
                float4 v = __ldg((const float4*)(x + ((size_t)(r*TM+mm)*TT + t)*IDIM) + kk);
                stage_f4(As, mm, kk, v);
            }
            if (tid == 0) {
                if (t > 0)
                    while (ld_acq(&g_done1[(t-1)*NBAND + r]) < NQ) { }
                if (t >= RING)   // ring-slot overwrite guard
                    while (ld_acq(&g_done2[(t-RING)*NBAND + r]) < NQ) { }
            }
            __syncthreads();
            // h1(t-1) half -> k 512..1023 (Whh)
            #pragma unroll
            for (int c = 0; c < 8; ++c) {
                int lin = tid + c*NTHR;
                int mm = lin >> 7, kk = lin & 127;
                int b  = r*TM + mm;
                const float* hp = (t == 0) ? (h0 + (size_t)b*HH)
                                           : &g_h1[(t-1)&(RING-1)][b][0];
                stage_f4(As, mm, 128 + kk, ldcg4(hp + kk*4));
            }
        } else {
            if (tid == 0) {
                if (t > 0)
                    while (ld_acq(&g_done2[(t-1)*NBAND + r]) < NQ) { }
                while (ld_acq(&g_done1[t*NBAND + r]) < NQ) { }
            }
            __syncthreads();
            // h1(t) -> k low (Wih slot); h2(t-1) -> k high (Whh slot)
            #pragma unroll
            for (int c = 0; c < 8; ++c) {
                int lin = tid + c*NTHR;
                int mm = lin >> 7, kk = lin & 127;
                int b  = r*TM + mm;
                stage_f4(As, mm, kk, ldcg4(&g_h1[t&(RING-1)][b][0] + kk*4));
                const float* hp = (t == 0) ? (h0 + (size_t)BB*HH + (size_t)b*HH)
                                           : (out + ((size_t)b*TT + (t-1))*HH);
                stage_f4(As, mm, 128 + kk, ldcg4(hp + kk*4));
            }
        }
        __syncthreads();

        // ================= GEMM: warp k-slice, thread 4x4, FMA2 over k-pairs =================
        unsigned long long acc[16];
        #pragma unroll
        for (int i = 0; i < 16; ++i) acc[i] = 0ull;

        const float* Wp = Wp0;
        #pragma unroll 4
        for (int kpl = 0; kpl < 64; ++kpl) {
            int kp = 64*w + kpl;
            int ks = (2*kp) ^ xr;            // swizzled k-index of the pair
            unsigned long long a0 = *(const unsigned long long*)(Ab + ks);
            unsigned long long a1 = *(const unsigned long long*)(Ab + AS_STRIDE   + ks);
            unsigned long long a2 = *(const unsigned long long*)(Ab + 2*AS_STRIDE + ks);
            unsigned long long a3 = *(const unsigned long long*)(Ab + 3*AS_STRIDE + ks);
            ulonglong2 W0 = *(const ulonglong2*)(Wp);        // cols 2cg, 2cg+1
            ulonglong2 W1 = *(const ulonglong2*)(Wp + 32);   // cols 16+2cg, 17+2cg
            fma2(acc[ 0], a0, W0.x); fma2(acc[ 1], a0, W0.y);
            fma2(acc[ 2], a0, W1.x); fma2(acc[ 3], a0, W1.y);
            fma2(acc[ 4], a1, W0.x); fma2(acc[ 5], a1, W0.y);
            fma2(acc[ 6], a1, W1.x); fma2(acc[ 7], a1, W1.y);
            fma2(acc[ 8], a2, W0.x); fma2(acc[ 9], a2, W0.y);
            fma2(acc[10], a2, W1.x); fma2(acc[11], a2, W1.y);
            fma2(acc[12], a3, W0.x); fma2(acc[13], a3, W0.y);
            fma2(acc[14], a3, W1.x); fma2(acc[15], a3, W1.y);
            Wp += 64;
        }

        // horizontal add (even-k + odd-k) and write partials (conflict-free: RMS=34)
        {
            float s[16];
            #pragma unroll
            for (int i = 0; i < 16; ++i) {
                float lo, hi;
                asm("mov.b64 {%0, %1}, %2;" : "=f"(lo), "=f"(hi) : "l"(acc[i]));
                s[i] = lo + hi;
            }
            float* Rw = Red + w*RWS + (4*rg)*RMS + cg*2;
            #pragma unroll
            for (int i = 0; i < 4; ++i) {
                *(float2*)(Rw + i*RMS)      = make_float2(s[i*4+0], s[i*4+1]);
                *(float2*)(Rw + i*RMS + 16) = make_float2(s[i*4+2], s[i*4+3]);
            }
        }
        __syncthreads();

        // ================= cross-warp reduce, bias, tanh, store =================
        float2 acc2 = make_float2(0.f, 0.f);
        #pragma unroll
        for (int ww = 0; ww < 8; ++ww) {
            float2 v = *(const float2*)(Red + ww*RWS + m_out*RMS + c_out);
            acc2.x += v.x; acc2.y += v.y;
        }
        float2 res;
        res.x = tanhf(acc2.x + bias.x);
        res.y = tanhf(acc2.y + bias.y);

        if (layer == 0) {
            *(float2*)&g_h1[t&(RING-1)][brow_o][hcol_o] = res;
            if (t == TT-1)
                *(float2*)(out + (size_t)BB*TT*HH + (size_t)brow_o*HH + hcol_o) = res;
        } else {
            *(float2*)(out + ((size_t)brow_o*TT + t)*HH + hcol_o) = res;
            if (t == TT-1)
                *(float2*)(out + (size_t)BB*TT*HH + (size_t)BB*HH
                               + (size_t)brow_o*HH + hcol_o) = res;
        }

        __syncthreads();
        if (tid == 0) {
            int* ctr = (layer == 0) ? &g_done1[t*NBAND + r] : &g_done2[t*NBAND + r];
            red_release(ctr);
        }
    }
}

extern "C" void kernel_launch(void* const* d_in, const int* in_sizes, int n_in,
                              void* d_out, int out_size)
{
    const float* x   = (const float*)d_in[0];
    const float* h0  = (const float*)d_in[1];
    const float* Wih = (const float*)d_in[2];
    const float* bih = (const float*)d_in[3];
    const float* Whh = (const float*)d_in[4];
    const float* bhh = (const float*)d_in[5];
    float* out = (float*)d_out;

    const size_t smem_bytes = (size_t)SMEM_FLOATS * sizeof(float); // ~209.3 KB
    cudaFuncSetAttribute(rnn_persistent,
                         cudaFuncAttributeMaxDynamicSharedMemorySize,
                         (int)smem_bytes);

    rnn_init_counters<<<(TT*NBAND + 255)/256, 256>>>();
    rnn_persistent<<<NCTA, NTHR, smem_bytes>>>(x, h0, Wih, bih, Whh, bhh, out);
}